// round 6
// baseline (speedup 1.0000x reference)
#include <cuda_runtime.h>

#define BATCH   16
#define NPTS    4096
#define NB      128
#define THREADS 64                   // 2 warps, homogeneous adjacent regions
#define QPW     64                   // queries per warp
#define GRIDX   (NPTS / (2 * QPW))   // 32 -> grid (32,16,2) = 1024 blocks
#define PPT     2
#define XMIN_F  (-6.0f)
#define XMAX_F  (6.0f)
#define WBUCK   ((XMAX_F - XMIN_F) / (float)NB)
#define BSCALE  ((float)NB / (XMAX_F - XMIN_F))

__device__ double g_acc[2];
__device__ float4 g_pts[2 * BATCH * NPTS];        // binned (x,y,z,||p||^2)
__device__ int    g_off[2 * BATCH * (NB + 1)];    // bucket prefix offsets

// One block per (batch, set): histogram -> prefix -> scatter into bucket order.
__global__ __launch_bounds__(256) void bin_kernel(
    const float* __restrict__ xyz1, const float* __restrict__ xyz2)
{
    const int b = blockIdx.x, set = blockIdx.y;
    if (b == 0 && set == 0 && threadIdx.x < 2) g_acc[threadIdx.x] = 0.0;

    const float* __restrict__ src = ((set == 0) ? xyz1 : xyz2) + (size_t)b * NPTS * 3;
    __shared__ int cnt[NB];
    __shared__ int cur[NB + 1];
    const int tid = threadIdx.x;

    for (int k = tid; k < NB; k += 256) cnt[k] = 0;
    __syncthreads();
    for (int i = tid; i < NPTS; i += 256) {
        float x = src[3 * i];
        int bk = min(max((int)((x - XMIN_F) * BSCALE), 0), NB - 1);
        atomicAdd(&cnt[bk], 1);
    }
    __syncthreads();
    if (tid == 0) {
        int s = 0;
        for (int k = 0; k < NB; k++) { cur[k] = s; s += cnt[k]; }
        cur[NB] = s;
    }
    __syncthreads();
    int* off = g_off + (set * BATCH + b) * (NB + 1);
    for (int k = tid; k <= NB; k += 256) off[k] = cur[k];
    __syncthreads();
    float4* dst = g_pts + (set * BATCH + b) * NPTS;
    for (int i = tid; i < NPTS; i += 256) {
        float x = src[3 * i], y = src[3 * i + 1], z = src[3 * i + 2];
        int bk = min(max((int)((x - XMIN_F) * BSCALE), 0), NB - 1);
        int pos = atomicAdd(&cur[bk], 1);
        dst[pos] = make_float4(x, y, z, x * x + y * y + z * z);
    }
}

// Scan one candidate bucket: t = ||c||^2 - 2*(q . c)  (true dist = t + ||q||^2)
#define SCAN_BUCKET(J)                                                        \
    {                                                                         \
        int s_ = off[J], e_ = off[(J) + 1];                                   \
        _Pragma("unroll 4")                                                   \
        for (int i_ = s_; i_ < e_; i_++) {                                    \
            float4 cv = cp[i_];                                               \
            _Pragma("unroll")                                                 \
            for (int p_ = 0; p_ < PPT; p_++) {                                \
                float t_ = fmaf(qx[p_], cv.x,                                 \
                           fmaf(qy[p_], cv.y,                                 \
                           fmaf(qz[p_], cv.z, cv.w)));                        \
                mn[p_] = fminf(mn[p_], t_);                                   \
            }                                                                 \
        }                                                                     \
    }

__global__ __launch_bounds__(THREADS) void chamfer_kernel()
{
    const int dir = blockIdx.z;
    const int b   = blockIdx.y;
    const float4* __restrict__ qp  = g_pts + (dir * BATCH + b) * NPTS;
    const float4* __restrict__ cp  = g_pts + ((1 - dir) * BATCH + b) * NPTS;
    const int*    __restrict__ off = g_off + ((1 - dir) * BATCH + b) * (NB + 1);
    const int tid  = threadIdx.x;
    const int lane = tid & 31;
    const int warp = tid >> 5;
    // Adjacent chunks per block: homogeneous cost within a block; 1024 blocks
    // of varying cost load-balance dynamically across SMs.
    const int q0 = (blockIdx.x * 2 + warp) * QPW;

    float qx[PPT], qy[PPT], qz[PPT], qs[PPT], rx[PPT], mn[PPT];
#pragma unroll
    for (int p = 0; p < PPT; p++) {
        float4 v = qp[q0 + lane + 32 * p];
        rx[p] = v.x;
        qx[p] = -2.0f * v.x; qy[p] = -2.0f * v.y; qz[p] = -2.0f * v.z;
        qs[p] = v.w;
        mn[p] = 3.4e38f;
    }

    // Warp-median x -> center bucket; scan outward with conservative pruning.
    float xm = __shfl_sync(0xffffffffu, rx[0], 16);
    int jc = min(max((int)((xm - XMIN_F) * BSCALE), 0), NB - 1);

    SCAN_BUCKET(jc);

    bool ldone = false, rdone = false;
    for (int r = 1; r < NB; r++) {
        if (ldone && rdone) break;
        if (!ldone) {
            int j = jc - r;
            if (j < 0) ldone = true;
            else {
                float el = XMIN_F + j * WBUCK;
                float er = el + WBUCK;
                bool done = true;
#pragma unroll
                for (int p = 0; p < PPT; p++) {
                    // bucket 0 holds clamped outliers: left bound = -inf
                    float g = fmaxf(0.0f, fmaxf((j > 0) ? (el - rx[p]) : 0.0f,
                                                rx[p] - er));
                    done = done && (g * g >= mn[p] + qs[p]);
                }
                if (__all_sync(0xffffffffu, done)) ldone = true;
                else SCAN_BUCKET(j);
            }
        }
        if (!rdone) {
            int j = jc + r;
            if (j >= NB) rdone = true;
            else {
                float el = XMIN_F + j * WBUCK;
                float er = el + WBUCK;
                bool done = true;
#pragma unroll
                for (int p = 0; p < PPT; p++) {
                    // bucket NB-1 holds clamped outliers: right bound = +inf
                    float g = fmaxf(0.0f, fmaxf(el - rx[p],
                                                (j < NB - 1) ? (rx[p] - er) : 0.0f));
                    done = done && (g * g >= mn[p] + qs[p]);
                }
                if (__all_sync(0xffffffffu, done)) rdone = true;
                else SCAN_BUCKET(j);
            }
        }
    }

    // True min distance = mn + ||q||^2; per-warp sum, one atomic per block.
    float s = 0.0f;
#pragma unroll
    for (int p = 0; p < PPT; p++) s += mn[p] + qs[p];
#pragma unroll
    for (int o = 16; o > 0; o >>= 1) s += __shfl_down_sync(0xffffffffu, s, o);

    __shared__ float red[2];
    if (lane == 0) red[warp] = s;
    __syncthreads();
    if (tid == 0) atomicAdd(&g_acc[dir], (double)(red[0] + red[1]));
}

__global__ void finalize_kernel(float* out) {
    if (threadIdx.x < 2)
        out[threadIdx.x] = (float)(g_acc[threadIdx.x] / (double)(BATCH * NPTS));
}

extern "C" void kernel_launch(void* const* d_in, const int* in_sizes, int n_in,
                              void* d_out, int out_size)
{
    const float* xyz1 = (const float*)d_in[0];
    const float* xyz2 = (const float*)d_in[1];
    float* out = (float*)d_out;

    bin_kernel<<<dim3(BATCH, 2), 256>>>(xyz1, xyz2);
    chamfer_kernel<<<dim3(GRIDX, BATCH, 2), THREADS>>>();   // (32,16,2) = 1024 blocks
    finalize_kernel<<<1, 32>>>(out);
}

// round 7
// speedup vs baseline: 3.0688x; 3.0688x over previous
#include <cuda_runtime.h>

#define BATCH   16
#define NPTS    4096
#define NB      128
#define THREADS 256
#define PPT     2
#define QPW     64                  // queries per warp
#define CHUNKS  (NPTS / QPW)        // 64 chunks per (dir,b)
#define GRIDX   (CHUNKS / 8)        // 8 blocks x 8 warps cover 64 chunks
#define XMIN_F  (-6.0f)
#define XMAX_F  (6.0f)
#define WBUCK   ((XMAX_F - XMIN_F) / (float)NB)
#define BSCALE  ((float)NB / (XMAX_F - XMIN_F))

__device__ double g_acc[2];
__device__ float4 g_pts[2 * BATCH * NPTS];        // binned (x,y,z,||p||^2)
__device__ int    g_off[2 * BATCH * (NB + 1)];    // bucket prefix offsets

// One block per (batch, set): histogram -> parallel prefix -> scatter.
__global__ __launch_bounds__(512) void bin_kernel(
    const float* __restrict__ xyz1, const float* __restrict__ xyz2)
{
    const int b = blockIdx.x, set = blockIdx.y;
    if (b == 0 && set == 0 && threadIdx.x < 2) g_acc[threadIdx.x] = 0.0;

    const float* __restrict__ src = ((set == 0) ? xyz1 : xyz2) + (size_t)b * NPTS * 3;
    __shared__ int cnt[NB];
    __shared__ int cur[NB + 1];
    __shared__ int wsum[NB / 32];
    const int tid = threadIdx.x;

    for (int k = tid; k < NB; k += 512) cnt[k] = 0;
    __syncthreads();
    for (int i = tid; i < NPTS; i += 512) {
        float x = src[3 * i];
        int bk = min(max((int)((x - XMIN_F) * BSCALE), 0), NB - 1);
        atomicAdd(&cnt[bk], 1);
    }
    __syncthreads();
    // Exclusive prefix over NB=128 buckets: 4 warps shfl-scan + offsets.
    int v = 0, s = 0;
    if (tid < NB) {
        v = cnt[tid]; s = v;
#pragma unroll
        for (int o = 1; o < 32; o <<= 1) {
            int n = __shfl_up_sync(0xffffffffu, s, o);
            if ((tid & 31) >= o) s += n;
        }
        if ((tid & 31) == 31) wsum[tid >> 5] = s;
    }
    __syncthreads();
    if (tid < NB) {
        int add = 0;
#pragma unroll
        for (int k = 0; k < NB / 32; k++) if (k < (tid >> 5)) add += wsum[k];
        cur[tid] = s - v + add;
        if (tid == NB - 1) cur[NB] = s + add;
    }
    __syncthreads();
    int* off = g_off + (set * BATCH + b) * (NB + 1);
    for (int k = tid; k <= NB; k += 512) off[k] = cur[k];
    float4* dst = g_pts + (set * BATCH + b) * NPTS;
    for (int i = tid; i < NPTS; i += 512) {
        float x = src[3 * i], y = src[3 * i + 1], z = src[3 * i + 2];
        int bk = min(max((int)((x - XMIN_F) * BSCALE), 0), NB - 1);
        int pos = atomicAdd(&cur[bk], 1);
        dst[pos] = make_float4(x, y, z, x * x + y * y + z * z);
    }
}

// Scan one candidate bucket from SMEM: t = ||c||^2 - 2*(q.c)
#define SCAN_BUCKET(J)                                                        \
    {                                                                         \
        int s_ = soff[J], e_ = soff[(J) + 1];                                 \
        _Pragma("unroll 4")                                                   \
        for (int i_ = s_; i_ < e_; i_++) {                                    \
            float4 cv = tile[i_];                                             \
            _Pragma("unroll")                                                 \
            for (int p_ = 0; p_ < PPT; p_++) {                                \
                float t_ = fmaf(qx[p_], cv.x,                                 \
                           fmaf(qy[p_], cv.y,                                 \
                           fmaf(qz[p_], cv.z, cv.w)));                        \
                mn[p_] = fminf(mn[p_], t_);                                   \
            }                                                                 \
        }                                                                     \
    }

__global__ __launch_bounds__(THREADS) void chamfer_kernel()
{
    const int dir = blockIdx.z;
    const int b   = blockIdx.y;
    extern __shared__ float4 tile[];                 // full candidate array, 64KB
    __shared__ int   soff[NB + 1];
    __shared__ float red[THREADS / 32];

    const float4* __restrict__ qp   = g_pts + (dir * BATCH + b) * NPTS;
    const float4* __restrict__ gc   = g_pts + ((1 - dir) * BATCH + b) * NPTS;
    const int*    __restrict__ goff = g_off + ((1 - dir) * BATCH + b) * (NB + 1);
    const int tid  = threadIdx.x;
    const int lane = tid & 31;
    const int warp = tid >> 5;

    // Stage candidates + offsets into SMEM (coalesced LDG.128 -> STS.128).
    for (int i = tid; i < NPTS; i += THREADS) tile[i] = gc[i];
    for (int k = tid; k <= NB; k += THREADS) soff[k] = goff[k];
    __syncthreads();

    // Mirror-paired chunks: warps 0-3 left side, warps 4-7 mirrored right side
    // -> every block has ~equal total cost (symmetric unimodal density).
    int chunk = (warp < 4) ? (blockIdx.x * 4 + warp)
                           : (CHUNKS - 1 - (blockIdx.x * 4 + (warp - 4)));
    int q0 = chunk * QPW;

    float qx[PPT], qy[PPT], qz[PPT], qs[PPT], rx[PPT], mn[PPT];
#pragma unroll
    for (int p = 0; p < PPT; p++) {
        float4 v = qp[q0 + lane + 32 * p];
        rx[p] = v.x;
        qx[p] = -2.0f * v.x; qy[p] = -2.0f * v.y; qz[p] = -2.0f * v.z;
        qs[p] = v.w;
        mn[p] = 3.4e38f;
    }

    // Warp-median x -> center bucket; outward scan with conservative pruning.
    float xm = __shfl_sync(0xffffffffu, rx[0], 16);
    int jc = min(max((int)((xm - XMIN_F) * BSCALE), 0), NB - 1);

    SCAN_BUCKET(jc);

    bool ldone = false, rdone = false;
    for (int r = 1; r < NB; r++) {
        if (ldone && rdone) break;
        if (!ldone) {
            int j = jc - r;
            if (j < 0) ldone = true;
            else {
                float el = XMIN_F + j * WBUCK;
                float er = el + WBUCK;
                bool done = true;
#pragma unroll
                for (int p = 0; p < PPT; p++) {
                    float g = fmaxf(0.0f, fmaxf((j > 0) ? (el - rx[p]) : 0.0f,
                                                rx[p] - er));
                    done = done && (g * g >= mn[p] + qs[p]);
                }
                if (__all_sync(0xffffffffu, done)) ldone = true;
                else SCAN_BUCKET(j);
            }
        }
        if (!rdone) {
            int j = jc + r;
            if (j >= NB) rdone = true;
            else {
                float el = XMIN_F + j * WBUCK;
                float er = el + WBUCK;
                bool done = true;
#pragma unroll
                for (int p = 0; p < PPT; p++) {
                    float g = fmaxf(0.0f, fmaxf(el - rx[p],
                                                (j < NB - 1) ? (rx[p] - er) : 0.0f));
                    done = done && (g * g >= mn[p] + qs[p]);
                }
                if (__all_sync(0xffffffffu, done)) rdone = true;
                else SCAN_BUCKET(j);
            }
        }
    }

    // True min distance = mn + ||q||^2; block reduce, one atomic per block.
    float s = 0.0f;
#pragma unroll
    for (int p = 0; p < PPT; p++) s += mn[p] + qs[p];
#pragma unroll
    for (int o = 16; o > 0; o >>= 1) s += __shfl_down_sync(0xffffffffu, s, o);
    if (lane == 0) red[warp] = s;
    __syncthreads();
    if (tid < THREADS / 32) {
        s = red[tid];
#pragma unroll
        for (int o = (THREADS / 64); o > 0; o >>= 1)
            s += __shfl_down_sync(0xffu, s, o);
        if (tid == 0) atomicAdd(&g_acc[dir], (double)s);
    }
}

__global__ void finalize_kernel(float* out) {
    if (threadIdx.x < 2)
        out[threadIdx.x] = (float)(g_acc[threadIdx.x] / (double)(BATCH * NPTS));
}

extern "C" void kernel_launch(void* const* d_in, const int* in_sizes, int n_in,
                              void* d_out, int out_size)
{
    const float* xyz1 = (const float*)d_in[0];
    const float* xyz2 = (const float*)d_in[1];
    float* out = (float*)d_out;

    static int smem_set = 0;
    if (!smem_set) {
        cudaFuncSetAttribute(chamfer_kernel,
                             cudaFuncAttributeMaxDynamicSharedMemorySize,
                             NPTS * (int)sizeof(float4));
        smem_set = 1;
    }

    bin_kernel<<<dim3(BATCH, 2), 512>>>(xyz1, xyz2);
    chamfer_kernel<<<dim3(GRIDX, BATCH, 2), THREADS,
                     NPTS * sizeof(float4)>>>();     // (8,16,2) = 256 blocks
    finalize_kernel<<<1, 32>>>(out);
}